// round 16
// baseline (speedup 1.0000x reference)
#include <cuda_runtime.h>
#include <cuda_fp16.h>
#include <math.h>
#include <cstdint>

#define BATCH 16384
#define OBS   512
#define ACT   256
#define NE    16
#define TOPK  4
#define TILE_M 128
#define NCHUNK 8                       // K chunks of 64
#define MAX_CHUNKS (BATCH / TILE_M)
#define CNT_STRIDE 64                  // pad counters to 256B -> distinct L2 slices

// ---------------- static device scratch ----------------
__device__ int    g_cnt[NE * CNT_STRIDE];
__device__ int    g_ridx[NE * BATCH];
__device__ float  g_w[NE * BATCH];
__device__ __half g_scr[(size_t)2 * 4 * BATCH * ACT];     // fp16 scratch [mat][slot][BATCH][ACT]
__device__ __half g_xt[(size_t)BATCH * OBS];              // fp16, k-permuted x
__device__ __half g_wt[(size_t)2 * NE * ACT * OBS];       // fp16, k-permuted weights

struct alignas(16) H8 { __half2 a, b, c, d; };

// m16n8k16 fp16 mma, fp32 accumulate
__device__ __forceinline__ void mma_f16(float* c,
                                        uint32_t a0, uint32_t a1, uint32_t a2, uint32_t a3,
                                        uint32_t b0, uint32_t b1) {
    asm volatile(
        "mma.sync.aligned.m16n8k16.row.col.f32.f16.f16.f32 "
        "{%0,%1,%2,%3}, {%4,%5,%6,%7}, {%8,%9}, {%0,%1,%2,%3};"
        : "+f"(c[0]), "+f"(c[1]), "+f"(c[2]), "+f"(c[3])
        : "r"(a0), "r"(a1), "r"(a2), "r"(a3), "r"(b0), "r"(b1));
}

__device__ __forceinline__ uint32_t smem_u32(const void* p) {
    uint32_t a;
    asm("{ .reg .u64 t; cvta.to.shared.u64 t, %1; cvt.u32.u64 %0, t; }" : "=r"(a) : "l"(p));
    return a;
}
__device__ __forceinline__ void cp16(uint32_t dst, const void* src, int sz) {
    asm volatile("cp.async.cg.shared.global [%0], [%1], 16, %2;"
                 :: "r"(dst), "l"(src), "r"(sz) : "memory");
}
#define CP_COMMIT() asm volatile("cp.async.commit_group;" ::: "memory")
#define CP_WAIT0()  asm volatile("cp.async.wait_group 0;" ::: "memory")

// pack a 16-k group (4 float4s, k contiguous) into permuted fp16:
// [k0,k1,k8,k9, k2,k3,k10,k11, k4,k5,k12,k13, k6,k7,k14,k15]
__device__ __forceinline__ void pack_group(float4 v0, float4 v1, float4 v2, float4 v3,
                                           H8* dst) {
    H8 o0, o1;
    o0.a = __floats2half2_rn(v0.x, v0.y); o0.b = __floats2half2_rn(v2.x, v2.y);
    o0.c = __floats2half2_rn(v0.z, v0.w); o0.d = __floats2half2_rn(v2.z, v2.w);
    o1.a = __floats2half2_rn(v1.x, v1.y); o1.b = __floats2half2_rn(v3.x, v3.y);
    o1.c = __floats2half2_rn(v1.z, v1.w); o1.d = __floats2half2_rn(v3.z, v3.w);
    dst[0] = o0; dst[1] = o1;
}

// ---------------- kernel 1: fused prep, classes interleaved by bx % 5 (R15 best) ----------------
// bx%5 in {0,1}: router (4096 blocks), {2,3}: x pack (4096), {4}: weight pack (2048)
__global__ void __launch_bounds__(128) prep_kernel(const float* __restrict__ x,
                                                   const float* __restrict__ rw,
                                                   const float* __restrict__ rb,
                                                   const float* __restrict__ mw,
                                                   const float* __restrict__ lw) {
    const int bx = blockIdx.x;
    const int cls = bx % 5;
    const int grp = bx / 5;            // 0..2047

    if (cls == 4) {
        int flat = grp * 128 + threadIdx.x;
        int g16 = flat & 31;
        int rowp = flat >> 5;
        int mat = rowp >> 12;
        const float4* s4 = (const float4*)((mat ? lw : mw) + (size_t)(rowp & 4095) * OBS + g16 * 16);
        pack_group(s4[0], s4[1], s4[2], s4[3], (H8*)(g_wt + (size_t)rowp * OBS + g16 * 16));
        return;
    }
    if (cls >= 2) {
        int xb = grp * 2 + (cls - 2);
        int flat = xb * 128 + threadIdx.x;
        int g16 = flat & 31;
        int row = flat >> 5;
        const float4* s4 = (const float4*)(x + (size_t)row * OBS + g16 * 16);
        pack_group(s4[0], s4[1], s4[2], s4[3], (H8*)(g_xt + (size_t)row * OBS + g16 * 16));
        return;
    }

    // ---- router: 1 row/warp, strided loads ----
    const int rbk = grp * 2 + cls;
    const int warp = threadIdx.x >> 5;
    const int lane = threadIdx.x & 31;
    const int b = rbk * 4 + warp;

    const float4* x4 = (const float4*)x;
    float4 xa[4];
#pragma unroll
    for (int i = 0; i < 4; i++) xa[i] = x4[(size_t)b * 128 + lane + 32 * i];

    float logit = 0.f;
#pragma unroll
    for (int e = 0; e < NE; e++) {
        const float4* w4 = (const float4*)rw + e * 128;
        float s = 0.f;
#pragma unroll
        for (int i = 0; i < 4; i++) {
            float4 w = __ldg(w4 + lane + 32 * i);
            s = fmaf(xa[i].x, w.x, fmaf(xa[i].y, w.y, fmaf(xa[i].z, w.z, fmaf(xa[i].w, w.w, s))));
        }
#pragma unroll
        for (int off = 16; off; off >>= 1) s += __shfl_xor_sync(0xffffffffu, s, off);
        if (lane == e) logit = s + rb[e];
    }

    float v = (lane < NE) ? logit : -1e30f;
    float m = v;
#pragma unroll
    for (int off = 16; off; off >>= 1) m = fmaxf(m, __shfl_xor_sync(0xffffffffu, m, off));
    float p = (lane < NE) ? expf(v - m) : 0.f;
    float s = p;
#pragma unroll
    for (int off = 16; off; off >>= 1) s += __shfl_xor_sync(0xffffffffu, s, off);
    float prob = p / s;

    float cur = (lane < NE) ? prob : -1.f;
#pragma unroll
    for (int slot = 0; slot < TOPK; slot++) {
        float mx = cur;
#pragma unroll
        for (int off = 16; off; off >>= 1) mx = fmaxf(mx, __shfl_xor_sync(0xffffffffu, mx, off));
        unsigned bal = __ballot_sync(0xffffffffu, cur == mx);
        int sel = __ffs(bal) - 1;
        if (lane == sel) {
            int pos = atomicAdd(&g_cnt[lane * CNT_STRIDE], 1);   // padded: 1 counter per L2 slice
            g_ridx[lane * BATCH + pos] = b * 4 + slot;
            g_w[lane * BATCH + pos]    = prob;
            cur = -1.f;
        }
    }
}

// ---------------- kernel 2: fp16 mma grouped GEMM, 128x128 tiles, 4 warps x (64x64), 2 CTAs/SM ----------------
#define ABYTES 16384u                  // 128 rows x 128 B (K-chunk 64)
#define BBYTES 16384u                  // 128 rows x 128 B
#define DYN_SMEM (2 * (ABYTES + BBYTES))   // 65536 per CTA

__global__ void __launch_bounds__(128, 2)
expert_mma_kernel(const float* __restrict__ mb, const float* __restrict__ lb) {
    const int e   = blockIdx.y;
    const int mat = blockIdx.z >> 1;
    const int nh  = blockIdx.z & 1;          // N half: cols nh*128..nh*128+127
    const int n   = g_cnt[e * CNT_STRIDE];
    const int start = blockIdx.x * TILE_M;
    if (start >= n) return;
    const int mrows = min(TILE_M, n - start);

    __shared__ int   bs[TILE_M];
    __shared__ int   ss[TILE_M];
    __shared__ float ws[TILE_M];
    extern __shared__ char smraw[];
    const uint32_t sb = smem_u32(smraw);

    const int t = threadIdx.x;
    if (t < TILE_M) {
        if (t < mrows) {
            int entry = g_ridx[e * BATCH + start + t];
            bs[t] = entry >> 2; ss[t] = entry & 3;
            ws[t] = g_w[e * BATCH + start + t];
        } else { bs[t] = 0; ss[t] = 0; ws[t] = 0.f; }
    }
    __syncthreads();

    const char* xt = (const char*)g_xt;
    const char* wt = (const char*)(g_wt + (size_t)((mat * NE + e) * ACT + nh * 128) * OBS);

    const int lane = t & 31;
    const int g  = lane >> 2;
    const int tg = lane & 3;
    const int wid = t >> 5;        // 0..3
    const int wm = wid & 1;        // warp M tile: rows wm*64..
    const int wn = wid >> 1;       // warp N tile: cols wn*64..

    // one K-chunk = 64 k = 128 B/row; swizzle: phys quad = q ^ (r&7)
    auto issue = [&](int kc, int buf) {
        const uint32_t abase = sb + buf * ABYTES;
#pragma unroll
        for (int i = 0; i < 8; i++) {               // A: 1024 quads
            int idx = t + 128 * i;
            int r = idx >> 3, q = idx & 7;
            const char* src = xt + (size_t)bs[r] * 1024 + kc * 128 + q * 16;
            uint32_t d = abase + (uint32_t)(r * 8 + (q ^ (r & 7))) * 16u;
            cp16(d, src, (r < mrows) ? 16 : 0);
        }
        const uint32_t bbase = sb + 2 * ABYTES + buf * BBYTES;
#pragma unroll
        for (int i = 0; i < 8; i++) {               // B: 1024 quads
            int idx = t + 128 * i;
            int r = idx >> 3, q = idx & 7;
            const char* src = wt + (size_t)r * 1024 + kc * 128 + q * 16;
            cp16(bbase + (uint32_t)(r * 8 + (q ^ (r & 7))) * 16u, src, 16);
        }
    };

    float acc[4][8][4];
#pragma unroll
    for (int im = 0; im < 4; im++)
#pragma unroll
        for (int in = 0; in < 8; in++)
#pragma unroll
            for (int c = 0; c < 4; c++) acc[im][in][c] = 0.f;

    issue(0, 0);
    CP_COMMIT();

    const int sw   = g;            // 3-bit row swizzle (r&7 == g for all frag rows)
    const int qsub = tg >> 1;
    const int bsel = (tg & 1) * 8;

#pragma unroll 1
    for (int kc = 0; kc < NCHUNK; kc++) {
        const int buf = kc & 1;
        CP_WAIT0();
        __syncthreads();
        if (kc + 1 < NCHUNK) { issue(kc + 1, buf ^ 1); CP_COMMIT(); }

        const char* Ab = smraw + buf * ABYTES;
        const char* Bb = smraw + 2 * ABYTES + buf * BBYTES;

#pragma unroll
        for (int ks = 0; ks < 4; ks++) {            // 4 x 16-k groups per chunk
            const int qoff = ((ks * 2 + qsub) ^ sw) * 16 + bsel;
            uint2 U[4], V[4];
#pragma unroll
            for (int im = 0; im < 4; im++) {
                const char* ap = Ab + (wm * 64 + im * 16 + g) * 128 + qoff;
                U[im] = *(const uint2*)ap;           // a0, a2
                V[im] = *(const uint2*)(ap + 1024);  // a1, a3 (row+8)
            }
#pragma unroll
            for (int in = 0; in < 8; in++) {
                uint2 W = *(const uint2*)(Bb + (wn * 64 + in * 8 + g) * 128 + qoff);
#pragma unroll
                for (int im = 0; im < 4; im++)
                    mma_f16(acc[im][in], U[im].x, V[im].x, U[im].y, V[im].y, W.x, W.y);
            }
        }
        __syncthreads();
    }

    // epilogue: w * (acc + bias) -> fp16 slot-indexed scratch (deterministic)
    const float* bias = (mat ? lb : mb) + e * ACT + nh * 128;
    float2 bv[8];
#pragma unroll
    for (int in = 0; in < 8; in++) {
        int c = wn * 64 + in * 8 + 2 * tg;
        bv[in] = make_float2(__ldg(bias + c), __ldg(bias + c + 1));
    }
#pragma unroll
    for (int im = 0; im < 4; im++) {
#pragma unroll
        for (int half = 0; half < 2; half++) {
            int r = wm * 64 + im * 16 + half * 8 + g;
            if (r < mrows) {
                float w = ws[r];
                __half* dst = g_scr + ((size_t)(mat * 4 + ss[r]) * BATCH + bs[r]) * ACT
                            + nh * 128 + wn * 64 + 2 * tg;
#pragma unroll
                for (int in = 0; in < 8; in++) {
                    float ox = w * (acc[im][in][half * 2 + 0] + bv[in].x);
                    float oy = w * (acc[im][in][half * 2 + 1] + bv[in].y);
                    *(__half2*)(dst + in * 8) = __floats2half2_rn(ox, oy);
                }
            }
        }
    }
}

// ---------------- kernel 3: combine slots (fp16 scratch), tanh squash (R15 best) ----------------
__global__ void __launch_bounds__(256) finalize_kernel(float* __restrict__ out) {
    const size_t N8 = (size_t)BATCH * ACT / 8;
    const size_t N4 = (size_t)BATCH * ACT / 4;
    const size_t base = (size_t)blockIdx.x * 512 + threadIdx.x;
    const uint4* s = (const uint4*)g_scr;
    float4* out4 = (float4*)out;

#pragma unroll
    for (int half = 0; half < 2; half++) {
        uint4 u[2][4];
#pragma unroll
        for (int v = 0; v < 2; v++) {
            size_t i = base + v * 256;
#pragma unroll
            for (int sl = 0; sl < 4; sl++) u[v][sl] = s[(half * 4 + sl) * N8 + i];
        }
#pragma unroll
        for (int v = 0; v < 2; v++) {
            size_t i = base + v * 256;
            float acc[8];
#pragma unroll
            for (int j = 0; j < 8; j++) acc[j] = 0.f;
#pragma unroll
            for (int sl = 0; sl < 4; sl++) {
                float2 f0 = __half22float2(*(__half2*)&u[v][sl].x);
                float2 f1 = __half22float2(*(__half2*)&u[v][sl].y);
                float2 f2 = __half22float2(*(__half2*)&u[v][sl].z);
                float2 f3 = __half22float2(*(__half2*)&u[v][sl].w);
                acc[0] += f0.x; acc[1] += f0.y; acc[2] += f1.x; acc[3] += f1.y;
                acc[4] += f2.x; acc[5] += f2.y; acc[6] += f3.x; acc[7] += f3.y;
            }
            if (half) {
#pragma unroll
                for (int j = 0; j < 8; j++) acc[j] = -5.f + 3.5f * (tanhf(acc[j]) + 1.f);
            }
            out4[half * N4 + 2 * i]     = make_float4(acc[0], acc[1], acc[2], acc[3]);
            out4[half * N4 + 2 * i + 1] = make_float4(acc[4], acc[5], acc[6], acc[7]);
        }
    }
}

// ---------------- launch ----------------
extern "C" void kernel_launch(void* const* d_in, const int* in_sizes, int n_in,
                              void* d_out, int out_size) {
    const float* x  = (const float*)d_in[0];
    const float* rw = (const float*)d_in[1];
    const float* rb = (const float*)d_in[2];
    const float* mw = (const float*)d_in[3];
    const float* mb = (const float*)d_in[4];
    const float* lw = (const float*)d_in[5];
    const float* lb = (const float*)d_in[6];
    float* out = (float*)d_out;

    cudaFuncSetAttribute(expert_mma_kernel,
                         cudaFuncAttributeMaxDynamicSharedMemorySize, DYN_SMEM);

    void* cntp = nullptr;
    cudaGetSymbolAddress(&cntp, g_cnt);
    cudaMemsetAsync(cntp, 0, sizeof(int) * NE * CNT_STRIDE);

    prep_kernel<<<10240, 128>>>(x, rw, rb, mw, lw);

    dim3 g2(MAX_CHUNKS, NE, 4);
    expert_mma_kernel<<<g2, 128, DYN_SMEM>>>(mb, lb);

    finalize_kernel<<<BATCH * ACT / 8 / 512, 256>>>(out);
}

// round 17
// speedup vs baseline: 1.0137x; 1.0137x over previous
#include <cuda_runtime.h>
#include <cuda_fp16.h>
#include <math.h>
#include <cstdint>

#define BATCH 16384
#define OBS   512
#define ACT   256
#define NE    16
#define TOPK  4
#define TILE_M 128
#define NCHUNK 4                       // K chunks of 128
#define MAX_CHUNKS (BATCH / TILE_M)
#define CNT_STRIDE 64                  // pad counters to 256B -> distinct L2 slices

// ---------------- static device scratch ----------------
__device__ int    g_cnt[NE * CNT_STRIDE];
__device__ int    g_ridx[NE * BATCH];
__device__ float  g_w[NE * BATCH];
__device__ __half g_scr[(size_t)2 * 4 * BATCH * ACT];     // fp16 scratch [mat][slot][BATCH][ACT]
__device__ __half g_xt[(size_t)BATCH * OBS];              // fp16, k-permuted x
__device__ __half g_wt[(size_t)2 * NE * ACT * OBS];       // fp16, k-permuted weights

struct alignas(16) H8 { __half2 a, b, c, d; };

// m16n8k16 fp16 mma, fp32 accumulate
__device__ __forceinline__ void mma_f16(float* c,
                                        uint32_t a0, uint32_t a1, uint32_t a2, uint32_t a3,
                                        uint32_t b0, uint32_t b1) {
    asm volatile(
        "mma.sync.aligned.m16n8k16.row.col.f32.f16.f16.f32 "
        "{%0,%1,%2,%3}, {%4,%5,%6,%7}, {%8,%9}, {%0,%1,%2,%3};"
        : "+f"(c[0]), "+f"(c[1]), "+f"(c[2]), "+f"(c[3])
        : "r"(a0), "r"(a1), "r"(a2), "r"(a3), "r"(b0), "r"(b1));
}

__device__ __forceinline__ uint32_t smem_u32(const void* p) {
    uint32_t a;
    asm("{ .reg .u64 t; cvta.to.shared.u64 t, %1; cvt.u32.u64 %0, t; }" : "=r"(a) : "l"(p));
    return a;
}
__device__ __forceinline__ void cp16(uint32_t dst, const void* src, int sz) {
    asm volatile("cp.async.cg.shared.global [%0], [%1], 16, %2;"
                 :: "r"(dst), "l"(src), "r"(sz) : "memory");
}
#define CP_COMMIT() asm volatile("cp.async.commit_group;" ::: "memory")
#define CP_WAIT0()  asm volatile("cp.async.wait_group 0;" ::: "memory")

// pack a 16-k group (4 float4s, k contiguous) into permuted fp16:
// [k0,k1,k8,k9, k2,k3,k10,k11, k4,k5,k12,k13, k6,k7,k14,k15]
__device__ __forceinline__ void pack_group(float4 v0, float4 v1, float4 v2, float4 v3,
                                           H8* dst) {
    H8 o0, o1;
    o0.a = __floats2half2_rn(v0.x, v0.y); o0.b = __floats2half2_rn(v2.x, v2.y);
    o0.c = __floats2half2_rn(v0.z, v0.w); o0.d = __floats2half2_rn(v2.z, v2.w);
    o1.a = __floats2half2_rn(v1.x, v1.y); o1.b = __floats2half2_rn(v3.x, v3.y);
    o1.c = __floats2half2_rn(v1.z, v1.w); o1.d = __floats2half2_rn(v3.z, v3.w);
    dst[0] = o0; dst[1] = o1;
}

// ---------------- kernel 1: fused prep, classes interleaved by bx % 3 ----------------
// bx%3 in {0,1}: router + fused x pack (4096 blocks), {2}: weight pack (2048)
__global__ void __launch_bounds__(128) prep_kernel(const float* __restrict__ x,
                                                   const float* __restrict__ rw,
                                                   const float* __restrict__ rb,
                                                   const float* __restrict__ mw,
                                                   const float* __restrict__ lw) {
    const int bx = blockIdx.x;
    const int cls = bx % 3;
    const int grp = bx / 3;            // 0..2047

    if (cls == 2) {
        // ---- weight convert: one 16-k group per thread ----
        int flat = grp * 128 + threadIdx.x;          // 262144 = 8192 rows x 32 groups
        int g16 = flat & 31;
        int rowp = flat >> 5;
        int mat = rowp >> 12;
        const float4* s4 = (const float4*)((mat ? lw : mw) + (size_t)(rowp & 4095) * OBS + g16 * 16);
        pack_group(s4[0], s4[1], s4[2], s4[3], (H8*)(g_wt + (size_t)rowp * OBS + g16 * 16));
        return;
    }

    // ---- router: 1 row/warp, strided loads + fused per-lane fp16 pack ----
    const int rbk = grp * 2 + cls;     // 0..4095
    const int warp = threadIdx.x >> 5;
    const int lane = threadIdx.x & 31;
    const int b = rbk * 4 + warp;

    const float4* x4 = (const float4*)x;
    float4 xa[4];
#pragma unroll
    for (int i = 0; i < 4; i++) xa[i] = x4[(size_t)b * 128 + lane + 32 * i];

    // fused x pack: lane L's xa[i] is member m = L&3 of pack-group g = (L>>2) + 8i.
    // Store the two half2 pieces exactly where pack_group would put them.
    {
        char* rowdst = (char*)(g_xt + (size_t)b * OBS);
        const int m = lane & 3;
        const int off_lo = (m & 1) * 16 + (m >> 1) * 4;
#pragma unroll
        for (int i = 0; i < 4; i++) {
            const int g16 = (lane >> 2) + 8 * i;
            __half2 lo = __floats2half2_rn(xa[i].x, xa[i].y);
            __half2 hi = __floats2half2_rn(xa[i].z, xa[i].w);
            *(__half2*)(rowdst + g16 * 32 + off_lo)     = lo;
            *(__half2*)(rowdst + g16 * 32 + off_lo + 8) = hi;
        }
    }

    float logit = 0.f;
#pragma unroll
    for (int e = 0; e < NE; e++) {
        const float4* w4 = (const float4*)rw + e * 128;
        float s = 0.f;
#pragma unroll
        for (int i = 0; i < 4; i++) {
            float4 w = __ldg(w4 + lane + 32 * i);
            s = fmaf(xa[i].x, w.x, fmaf(xa[i].y, w.y, fmaf(xa[i].z, w.z, fmaf(xa[i].w, w.w, s))));
        }
#pragma unroll
        for (int off = 16; off; off >>= 1) s += __shfl_xor_sync(0xffffffffu, s, off);
        if (lane == e) logit = s + rb[e];
    }

    float v = (lane < NE) ? logit : -1e30f;
    float m = v;
#pragma unroll
    for (int off = 16; off; off >>= 1) m = fmaxf(m, __shfl_xor_sync(0xffffffffu, m, off));
    float p = (lane < NE) ? expf(v - m) : 0.f;
    float s = p;
#pragma unroll
    for (int off = 16; off; off >>= 1) s += __shfl_xor_sync(0xffffffffu, s, off);
    float prob = p / s;

    float cur = (lane < NE) ? prob : -1.f;
#pragma unroll
    for (int slot = 0; slot < TOPK; slot++) {
        float mx = cur;
#pragma unroll
        for (int off = 16; off; off >>= 1) mx = fmaxf(mx, __shfl_xor_sync(0xffffffffu, mx, off));
        unsigned bal = __ballot_sync(0xffffffffu, cur == mx);
        int sel = __ffs(bal) - 1;
        if (lane == sel) {
            int pos = atomicAdd(&g_cnt[lane * CNT_STRIDE], 1);   // padded: 1 counter per L2 slice
            g_ridx[lane * BATCH + pos] = b * 4 + slot;
            g_w[lane * BATCH + pos]    = prob;
            cur = -1.f;
        }
    }
}

// ---------------- kernel 2: fp16 mma grouped GEMM, 8 warps x (64x64) tiles (R15 best) ----------------
#define ABYTES 32768u                  // 128 rows x 256 B
#define BBYTES 65536u                  // 256 rows x 256 B
#define DYN_SMEM (2 * (ABYTES + BBYTES))   // 196608

__global__ void __launch_bounds__(256, 1)
expert_mma_kernel(const float* __restrict__ mb, const float* __restrict__ lb) {
    const int e   = blockIdx.y;
    const int mat = blockIdx.z;
    const int n   = g_cnt[e * CNT_STRIDE];
    const int start = blockIdx.x * TILE_M;
    if (start >= n) return;
    const int mrows = min(TILE_M, n - start);

    __shared__ int   bs[TILE_M];
    __shared__ int   ss[TILE_M];
    __shared__ float ws[TILE_M];
    extern __shared__ char smraw[];
    const uint32_t sb = smem_u32(smraw);

    const int t = threadIdx.x;
    if (t < TILE_M) {
        if (t < mrows) {
            int entry = g_ridx[e * BATCH + start + t];
            bs[t] = entry >> 2; ss[t] = entry & 3;
            ws[t] = g_w[e * BATCH + start + t];
        } else { bs[t] = 0; ss[t] = 0; ws[t] = 0.f; }
    }
    __syncthreads();

    const char* xt = (const char*)g_xt;
    const char* wt = (const char*)(g_wt + (size_t)((mat * NE + e) * ACT) * OBS);

    const int lane = t & 31;
    const int g  = lane >> 2;
    const int tg = lane & 3;
    const int wid = t >> 5;        // 0..7
    const int wm = wid & 1;        // warp M tile: rows wm*64..
    const int wn = wid >> 1;       // warp N tile: cols wn*64..

    auto issue = [&](int kc, int buf) {
        const uint32_t abase = sb + buf * ABYTES;
#pragma unroll
        for (int i = 0; i < 8; i++) {               // A: 2048 quads
            int idx = t + 256 * i;
            int r = idx >> 4, q = idx & 15;
            const char* src = xt + (size_t)bs[r] * 1024 + kc * 256 + q * 16;
            uint32_t d = abase + (uint32_t)(r * 16 + (q ^ ((r & 7) << 1))) * 16u;
            cp16(d, src, (r < mrows) ? 16 : 0);
        }
        const uint32_t bbase = sb + 2 * ABYTES + buf * BBYTES;
#pragma unroll
        for (int i = 0; i < 16; i++) {              // B: 4096 quads
            int idx = t + 256 * i;
            int r = idx >> 4, q = idx & 15;
            const char* src = wt + (size_t)r * 1024 + kc * 256 + q * 16;
            cp16(bbase + (uint32_t)(r * 16 + (q ^ ((r & 7) << 1))) * 16u, src, 16);
        }
    };

    float acc[4][8][4];
#pragma unroll
    for (int im = 0; im < 4; im++)
#pragma unroll
        for (int in = 0; in < 8; in++)
#pragma unroll
            for (int c = 0; c < 4; c++) acc[im][in][c] = 0.f;

    issue(0, 0);
    CP_COMMIT();

    const int sw   = g << 1;
    const int qsub = tg >> 1;
    const int bsel = (tg & 1) * 8;

#pragma unroll 1
    for (int kc = 0; kc < NCHUNK; kc++) {
        const int buf = kc & 1;
        CP_WAIT0();
        __syncthreads();
        if (kc + 1 < NCHUNK) { issue(kc + 1, buf ^ 1); CP_COMMIT(); }

        const char* Ab = smraw + buf * ABYTES;
        const char* Bb = smraw + 2 * ABYTES + buf * BBYTES;

#pragma unroll
        for (int ks = 0; ks < 8; ks++) {
            const int qoff = ((ks * 2 + qsub) ^ sw) * 16 + bsel;
            uint2 U[4], V[4];
#pragma unroll
            for (int im = 0; im < 4; im++) {
                const char* ap = Ab + (wm * 64 + im * 16 + g) * 256 + qoff;
                U[im] = *(const uint2*)ap;           // a0, a2
                V[im] = *(const uint2*)(ap + 2048);  // a1, a3 (row+8)
            }
#pragma unroll
            for (int in = 0; in < 8; in++) {
                uint2 W = *(const uint2*)(Bb + (wn * 64 + in * 8 + g) * 256 + qoff);
#pragma unroll
                for (int im = 0; im < 4; im++)
                    mma_f16(acc[im][in], U[im].x, V[im].x, U[im].y, V[im].y, W.x, W.y);
            }
        }
        __syncthreads();
    }

    // epilogue: w * (acc + bias) -> fp16 slot-indexed scratch (deterministic)
    const float* bias = (mat ? lb : mb) + e * ACT;
    float2 bv[8];
#pragma unroll
    for (int in = 0; in < 8; in++) {
        int c = wn * 64 + in * 8 + 2 * tg;
        bv[in] = make_float2(__ldg(bias + c), __ldg(bias + c + 1));
    }
#pragma unroll
    for (int im = 0; im < 4; im++) {
#pragma unroll
        for (int half = 0; half < 2; half++) {
            int r = wm * 64 + im * 16 + half * 8 + g;
            if (r < mrows) {
                float w = ws[r];
                __half* dst = g_scr + ((size_t)(mat * 4 + ss[r]) * BATCH + bs[r]) * ACT
                            + wn * 64 + 2 * tg;
#pragma unroll
                for (int in = 0; in < 8; in++) {
                    float ox = w * (acc[im][in][half * 2 + 0] + bv[in].x);
                    float oy = w * (acc[im][in][half * 2 + 1] + bv[in].y);
                    *(__half2*)(dst + in * 8) = __floats2half2_rn(ox, oy);
                }
            }
        }
    }
}

// ---------------- kernel 3: combine slots (fp16 scratch), tanh squash (R15 best) ----------------
__global__ void __launch_bounds__(256) finalize_kernel(float* __restrict__ out) {
    const size_t N8 = (size_t)BATCH * ACT / 8;
    const size_t N4 = (size_t)BATCH * ACT / 4;
    const size_t base = (size_t)blockIdx.x * 512 + threadIdx.x;
    const uint4* s = (const uint4*)g_scr;
    float4* out4 = (float4*)out;

#pragma unroll
    for (int half = 0; half < 2; half++) {
        uint4 u[2][4];
#pragma unroll
        for (int v = 0; v < 2; v++) {
            size_t i = base + v * 256;
#pragma unroll
            for (int sl = 0; sl < 4; sl++) u[v][sl] = s[(half * 4 + sl) * N8 + i];
        }
#pragma unroll
        for (int v = 0; v < 2; v++) {
            size_t i = base + v * 256;
            float acc[8];
#pragma unroll
            for (int j = 0; j < 8; j++) acc[j] = 0.f;
#pragma unroll
            for (int sl = 0; sl < 4; sl++) {
                float2 f0 = __half22float2(*(__half2*)&u[v][sl].x);
                float2 f1 = __half22float2(*(__half2*)&u[v][sl].y);
                float2 f2 = __half22float2(*(__half2*)&u[v][sl].z);
                float2 f3 = __half22float2(*(__half2*)&u[v][sl].w);
                acc[0] += f0.x; acc[1] += f0.y; acc[2] += f1.x; acc[3] += f1.y;
                acc[4] += f2.x; acc[5] += f2.y; acc[6] += f3.x; acc[7] += f3.y;
            }
            if (half) {
#pragma unroll
                for (int j = 0; j < 8; j++) acc[j] = -5.f + 3.5f * (tanhf(acc[j]) + 1.f);
            }
            out4[half * N4 + 2 * i]     = make_float4(acc[0], acc[1], acc[2], acc[3]);
            out4[half * N4 + 2 * i + 1] = make_float4(acc[4], acc[5], acc[6], acc[7]);
        }
    }
}

// ---------------- launch ----------------
extern "C" void kernel_launch(void* const* d_in, const int* in_sizes, int n_in,
                              void* d_out, int out_size) {
    const float* x  = (const float*)d_in[0];
    const float* rw = (const float*)d_in[1];
    const float* rb = (const float*)d_in[2];
    const float* mw = (const float*)d_in[3];
    const float* mb = (const float*)d_in[4];
    const float* lw = (const float*)d_in[5];
    const float* lb = (const float*)d_in[6];
    float* out = (float*)d_out;

    cudaFuncSetAttribute(expert_mma_kernel,
                         cudaFuncAttributeMaxDynamicSharedMemorySize, DYN_SMEM);

    void* cntp = nullptr;
    cudaGetSymbolAddress(&cntp, g_cnt);
    cudaMemsetAsync(cntp, 0, sizeof(int) * NE * CNT_STRIDE);

    prep_kernel<<<6144, 128>>>(x, rw, rb, mw, lw);

    dim3 g2(MAX_CHUNKS, NE, 2);
    expert_mma_kernel<<<g2, 256, DYN_SMEM>>>(mb, lb);

    finalize_kernel<<<BATCH * ACT / 8 / 512, 256>>>(out);
}